// round 4
// baseline (speedup 1.0000x reference)
#include <cuda_runtime.h>
#include <math.h>
#include <float.h>

#define LEVELS 16
#define MAXRES 2048
#define BMAX   (1 << 20)
#define NB     (1 << 18)          // 18-bit Morton bins (6 bits/axis)
#define SCAN_BLK 1024
#define NBLK   (NB / SCAN_BLK)    // 256
#define TILE_CAP 5120             // float2 cells of smem tile (40KB)

struct LP { float resm1[LEVELS]; float fres[LEVELS]; };

// ---------------- scratch ----------------------------------------------------
__device__ unsigned int g_hist[NB];
__device__ unsigned int g_bsum[NBLK];
__device__ unsigned int g_key[BMAX];
__device__ float4       g_spos[BMAX];

// ---------------- helpers ----------------------------------------------------
__device__ __forceinline__ int quantize(float c, float fres) {
    return (int)__fmul_rn(__fdiv_rn(c, fres), 2047.0f);
}

__device__ __forceinline__ unsigned int expand3(unsigned int v) {
    v = (v | (v << 16)) & 0x030000FFu;
    v = (v | (v <<  8)) & 0x0300F00Fu;
    v = (v | (v <<  4)) & 0x030C30C3u;
    v = (v | (v <<  2)) & 0x09249249u;
    return v;
}

__device__ __forceinline__ unsigned int morton_key(float x, float y, float z) {
    int ix = (int)(x * 64.0f), iy = (int)(y * 64.0f), iz = (int)(z * 64.0f);
    unsigned int kx = (unsigned int)max(0, min(63, ix));
    unsigned int ky = (unsigned int)max(0, min(63, iy));
    unsigned int kz = (unsigned int)max(0, min(63, iz));
    return expand3(kx) | (expand3(ky) << 1) | (expand3(kz) << 2);
}

// ---------------- sort pipeline ----------------------------------------------
__global__ void zero_hist_kernel() {
    int i = blockIdx.x * blockDim.x + threadIdx.x;
    if (i < NB) g_hist[i] = 0u;
}

__global__ void hist_kernel(const float* __restrict__ positions, int B) {
    int i = blockIdx.x * blockDim.x + threadIdx.x;
    if (i >= B) return;
    float x = positions[3*i+0], y = positions[3*i+1], z = positions[3*i+2];
    unsigned int k = morton_key(x, y, z);
    g_key[i] = k;
    atomicAdd(&g_hist[k], 1u);
}

__global__ void scanA_kernel() {
    __shared__ unsigned int s[SCAN_BLK];
    int tid = threadIdx.x;
    int gid = blockIdx.x * SCAN_BLK + tid;
    unsigned int v = g_hist[gid];
    s[tid] = v;
    __syncthreads();
    for (int off = 1; off < SCAN_BLK; off <<= 1) {
        unsigned int t = (tid >= off) ? s[tid - off] : 0u;
        __syncthreads();
        s[tid] += t;
        __syncthreads();
    }
    g_hist[gid] = s[tid] - v;
    if (tid == SCAN_BLK - 1) g_bsum[blockIdx.x] = s[tid];
}

__global__ void scanB_kernel() {
    __shared__ unsigned int s[NBLK];
    int tid = threadIdx.x;
    unsigned int v = g_bsum[tid];
    s[tid] = v;
    __syncthreads();
    for (int off = 1; off < NBLK; off <<= 1) {
        unsigned int t = (tid >= off) ? s[tid - off] : 0u;
        __syncthreads();
        s[tid] += t;
        __syncthreads();
    }
    g_bsum[tid] = s[tid] - v;
}

__global__ void scanC_kernel() {
    int i = blockIdx.x * blockDim.x + threadIdx.x;
    if (i < NB) g_hist[i] += g_bsum[i / SCAN_BLK];
}

__global__ void scatter_kernel(const float* __restrict__ positions, int B) {
    int i = blockIdx.x * blockDim.x + threadIdx.x;
    if (i >= B) return;
    float x = positions[3*i+0], y = positions[3*i+1], z = positions[3*i+2];
    unsigned int k = g_key[i];
    unsigned int dst = atomicAdd(&g_hist[k], 1u);
    g_spos[dst] = make_float4(x, y, z, __int_as_float(i));
}

// ---------------- main encoder -----------------------------------------------
__global__ void __launch_bounds__(256) triplane_kernel(
    const float* __restrict__ table,
    float* __restrict__ out, int B, LP lp)
{
    __shared__ float2 tile[TILE_CAP];
    __shared__ float  red_mn[3][8];
    __shared__ float  red_mx[3][8];
    __shared__ float  s_bbox[6];

    int tid = threadIdx.x;
    int i = blockIdx.x * 256 + tid;
    bool valid = (i < B);

    float px = 0.f, py = 0.f, pz = 0.f;
    int b = 0;
    if (valid) {
        float4 p = g_spos[i];
        px = p.x; py = p.y; pz = p.z;
        b = __float_as_int(p.w);
    }

    // ---- block bbox over positions (valid lanes only) ----
    {
        float mn[3] = { valid ? px :  FLT_MAX, valid ? py :  FLT_MAX, valid ? pz :  FLT_MAX };
        float mx[3] = { valid ? px : -FLT_MAX, valid ? py : -FLT_MAX, valid ? pz : -FLT_MAX };
#pragma unroll
        for (int o = 16; o > 0; o >>= 1) {
#pragma unroll
            for (int d = 0; d < 3; d++) {
                mn[d] = fminf(mn[d], __shfl_xor_sync(0xFFFFFFFFu, mn[d], o));
                mx[d] = fmaxf(mx[d], __shfl_xor_sync(0xFFFFFFFFu, mx[d], o));
            }
        }
        int w = tid >> 5;
        if ((tid & 31) == 0) {
#pragma unroll
            for (int d = 0; d < 3; d++) { red_mn[d][w] = mn[d]; red_mx[d][w] = mx[d]; }
        }
        __syncthreads();
        if (tid < 6) {
            int d = tid >> 1;
            bool isMax = tid & 1;
            float v = isMax ? -FLT_MAX : FLT_MAX;
#pragma unroll
            for (int ww = 0; ww < 8; ww++)
                v = isMax ? fmaxf(v, red_mx[d][ww]) : fminf(v, red_mn[d][ww]);
            s_bbox[tid] = v;
        }
        __syncthreads();
    }
    float mnx = s_bbox[0], mxx = s_bbox[1];
    float mny = s_bbox[2], mxy = s_bbox[3];
    float mnz = s_bbox[4], mxz = s_bbox[5];

    const float2* t0 = (const float2*)table;
    const float2* t1 = t0 + MAXRES*MAXRES;
    const float2* t2 = t1 + MAXRES*MAXRES;

    float r[2*LEVELS];

#pragma unroll
    for (int l = 0; l < LEVELS; l++) {
        float resm1 = lp.resm1[l];
        float fres  = lp.fres[l];

        // per-point grid coords (exact reference arithmetic)
        float posx = __fadd_rn(__fmul_rn(px, resm1), 0.5f);
        float posy = __fadd_rn(__fmul_rn(py, resm1), 0.5f);
        float posz = __fadd_rn(__fmul_rn(pz, resm1), 0.5f);
        float gx = floorf(posx), gy = floorf(posy), gz = floorf(posz);
        float fx = posx - gx, fy = posy - gy, fz = posz - gz;
        float omx = 1.0f - fx, omy = 1.0f - fy, omz = 1.0f - fz;

        float wa0 = omx*omy, wa1 = fx*omy, wa2 = omx*fy, wa3 = fx*fy;
        float wb0 = omy*omz, wb1 = fy*omz, wb2 = omy*fz, wb3 = fy*fz;
        float wc0 = omz*omx, wc1 = fz*omx, wc2 = omz*fx, wc3 = fz*fx;

        // block tile bounds (monotone => exact)
        float gx0 = floorf(__fadd_rn(__fmul_rn(mnx, resm1), 0.5f));
        float gx1 = floorf(__fadd_rn(__fmul_rn(mxx, resm1), 0.5f));
        float gy0 = floorf(__fadd_rn(__fmul_rn(mny, resm1), 0.5f));
        float gy1 = floorf(__fadd_rn(__fmul_rn(mxy, resm1), 0.5f));
        float gz0 = floorf(__fadd_rn(__fmul_rn(mnz, resm1), 0.5f));
        float gz1 = floorf(__fadd_rn(__fmul_rn(mxz, resm1), 0.5f));
        int nx = (int)(gx1 - gx0) + 2;
        int ny = (int)(gy1 - gy0) + 2;
        int nz = (int)(gz1 - gz0) + 2;

        int n01 = nx * ny;            // plane0 tile (i=x, j=y)
        int n12 = ny * nz;            // plane1 tile (i=y, j=z)
        int n20 = nz * nx;            // plane2 tile (i=z, j=x)
        int total = n01 + n12 + n20;
        bool staged = (total <= TILE_CAP);   // block-uniform

        float2 a00,a10,a01,a11, b00,b10,b01,b11, c00,c10,c01,c11;

        if (staged) {
            __syncthreads();   // previous level's consumers done
            for (int k = tid; k < total; k += 256) {
                int p, rem, ii, jj;
                const float2* tp;
                float fi, fj;
                if (k < n01)            { p=0; rem=k;           ii=rem%nx; jj=rem/nx; tp=t0; fi=gx0; fj=gy0; }
                else if (k < n01+n12)   { p=1; rem=k-n01;       ii=rem%ny; jj=rem/ny; tp=t1; fi=gy0; fj=gz0; }
                else                    { p=2; rem=k-n01-n12;   ii=rem%nz; jj=rem/nz; tp=t2; fi=gz0; fj=gx0; }
                int c0 = quantize(fi + (float)ii, fres);
                int c1 = quantize(fj + (float)jj, fres);
                tile[k] = __ldg(&tp[c0 + c1*MAXRES]);
            }
            __syncthreads();

            int ix = (int)(gx - gx0);
            int iy = (int)(gy - gy0);
            int iz = (int)(gz - gz0);

            const float2* T0 = tile;
            const float2* T1 = tile + n01;
            const float2* T2 = tile + n01 + n12;

            a00 = T0[iy*nx + ix];       a10 = T0[iy*nx + ix+1];
            a01 = T0[(iy+1)*nx + ix];   a11 = T0[(iy+1)*nx + ix+1];

            b00 = T1[iz*ny + iy];       b10 = T1[iz*ny + iy+1];
            b01 = T1[(iz+1)*ny + iy];   b11 = T1[(iz+1)*ny + iy+1];

            c00 = T2[ix*nz + iz];       c10 = T2[ix*nz + iz+1];
            c01 = T2[(ix+1)*nz + iz];   c11 = T2[(ix+1)*nz + iz+1];
        } else {
            int cxm = quantize(gx, fres), cxp = quantize(gx + 1.0f, fres);
            int cym = quantize(gy, fres), cyp = quantize(gy + 1.0f, fres);
            int czm = quantize(gz, fres), czp = quantize(gz + 1.0f, fres);

            a00 = __ldg(&t0[cxm + cym*MAXRES]);
            a10 = __ldg(&t0[cxp + cym*MAXRES]);
            a01 = __ldg(&t0[cxm + cyp*MAXRES]);
            a11 = __ldg(&t0[cxp + cyp*MAXRES]);

            b00 = __ldg(&t1[cym + czm*MAXRES]);
            b10 = __ldg(&t1[cyp + czm*MAXRES]);
            b01 = __ldg(&t1[cym + czp*MAXRES]);
            b11 = __ldg(&t1[cyp + czp*MAXRES]);

            c00 = __ldg(&t2[czm + cxm*MAXRES]);
            c10 = __ldg(&t2[czp + cxm*MAXRES]);
            c01 = __ldg(&t2[czm + cxp*MAXRES]);
            c11 = __ldg(&t2[czp + cxp*MAXRES]);
        }

        float p0x = ((wa0*a00.x + wa1*a10.x) + wa2*a01.x) + wa3*a11.x;
        float p0y = ((wa0*a00.y + wa1*a10.y) + wa2*a01.y) + wa3*a11.y;
        float p1x = ((wb0*b00.x + wb1*b10.x) + wb2*b01.x) + wb3*b11.x;
        float p1y = ((wb0*b00.y + wb1*b10.y) + wb2*b01.y) + wb3*b11.y;
        float p2x = ((wc0*c00.x + wc1*c10.x) + wc2*c01.x) + wc3*c11.x;
        float p2y = ((wc0*c00.y + wc1*c10.y) + wc2*c01.y) + wc3*c11.y;

        r[l]          = (p0x*p1x)*p2x;
        r[LEVELS + l] = (p0y*p1y)*p2y;
    }

    if (valid) {
        float4* o4 = (float4*)(out + (size_t)b * (2*LEVELS));
#pragma unroll
        for (int k = 0; k < 8; k++)
            o4[k] = make_float4(r[4*k+0], r[4*k+1], r[4*k+2], r[4*k+3]);
    }
}

// ---------------- launch -----------------------------------------------------
extern "C" void kernel_launch(void* const* d_in, const int* in_sizes, int n_in,
                              void* d_out, int out_size) {
    const float* positions = (const float*)d_in[0];
    const float* table     = (const float*)d_in[1];
    float* out             = (float*)d_out;
    int B = in_sizes[0] / 3;

    LP lp;
    double logb = log(2048.0 / 16.0) / 15.0;
    for (int l = 0; l < LEVELS; l++) {
        double scale = 16.0 * exp((double)l * logb) - 1.0;
        int res = (int)ceil(scale) + 1;
        lp.resm1[l] = (float)(res - 1);
        lp.fres[l]  = (float)res;
    }

    int threads = 256;
    int blocks  = (B + threads - 1) / threads;

    zero_hist_kernel<<<NB / 256, 256>>>();
    hist_kernel<<<blocks, threads>>>(positions, B);
    scanA_kernel<<<NBLK, SCAN_BLK>>>();
    scanB_kernel<<<1, NBLK>>>();
    scanC_kernel<<<NB / 256, 256>>>();
    scatter_kernel<<<blocks, threads>>>(positions, B);
    triplane_kernel<<<blocks, threads>>>(table, out, B, lp);
}

// round 5
// speedup vs baseline: 1.1893x; 1.1893x over previous
#include <cuda_runtime.h>
#include <math.h>

#define LEVELS 16
#define MAXRES 2048
#define BMAX   (1 << 20)
#define NB     (1 << 18)          // 18-bit Morton bins (6 bits/axis)
#define SCAN_BLK 1024
#define NBLK   (NB / SCAN_BLK)    // 256
#define LUTCAP 8192

struct LP { float resm1[LEVELS]; float fres[LEVELS]; int off[LEVELS+1]; };

// ---------------- scratch ----------------------------------------------------
__device__ unsigned int g_hist[NB];
__device__ unsigned int g_bsum[NBLK];
__device__ unsigned int g_key[BMAX];
__device__ float4       g_spos[BMAX];
__device__ unsigned short g_lut[LUTCAP];

// ---------------- helpers ----------------------------------------------------
__device__ __forceinline__ int quantize(float c, float fres) {
    return (int)__fmul_rn(__fdiv_rn(c, fres), 2047.0f);
}

__device__ __forceinline__ unsigned int expand3(unsigned int v) {
    v = (v | (v << 16)) & 0x030000FFu;
    v = (v | (v <<  8)) & 0x0300F00Fu;
    v = (v | (v <<  4)) & 0x030C30C3u;
    v = (v | (v <<  2)) & 0x09249249u;
    return v;
}

__device__ __forceinline__ unsigned int morton_key(float x, float y, float z) {
    int ix = (int)(x * 64.0f), iy = (int)(y * 64.0f), iz = (int)(z * 64.0f);
    unsigned int kx = (unsigned int)max(0, min(63, ix));
    unsigned int ky = (unsigned int)max(0, min(63, iy));
    unsigned int kz = (unsigned int)max(0, min(63, iz));
    return expand3(kx) | (expand3(ky) << 1) | (expand3(kz) << 2);
}

// ---------------- LUT build ---------------------------------------------------
__global__ void build_lut_kernel(LP lp) {
    int e = blockIdx.x * blockDim.x + threadIdx.x;
    if (e >= lp.off[LEVELS]) return;
    int l = 0;
#pragma unroll
    for (int k = 0; k < LEVELS; k++)
        if (e >= lp.off[k]) l = k;
    int c = e - lp.off[l];
    g_lut[e] = (unsigned short)quantize((float)c, lp.fres[l]);
}

// ---------------- sort pipeline ----------------------------------------------
__global__ void zero_hist_kernel() {
    int i = blockIdx.x * blockDim.x + threadIdx.x;
    if (i < NB) g_hist[i] = 0u;
}

__global__ void hist_kernel(const float* __restrict__ positions, int B) {
    int i = blockIdx.x * blockDim.x + threadIdx.x;
    if (i >= B) return;
    float x = positions[3*i+0], y = positions[3*i+1], z = positions[3*i+2];
    unsigned int k = morton_key(x, y, z);
    g_key[i] = k;
    atomicAdd(&g_hist[k], 1u);
}

__global__ void scanA_kernel() {
    __shared__ unsigned int s[SCAN_BLK];
    int tid = threadIdx.x;
    int gid = blockIdx.x * SCAN_BLK + tid;
    unsigned int v = g_hist[gid];
    s[tid] = v;
    __syncthreads();
    for (int off = 1; off < SCAN_BLK; off <<= 1) {
        unsigned int t = (tid >= off) ? s[tid - off] : 0u;
        __syncthreads();
        s[tid] += t;
        __syncthreads();
    }
    g_hist[gid] = s[tid] - v;
    if (tid == SCAN_BLK - 1) g_bsum[blockIdx.x] = s[tid];
}

__global__ void scanB_kernel() {
    __shared__ unsigned int s[NBLK];
    int tid = threadIdx.x;
    unsigned int v = g_bsum[tid];
    s[tid] = v;
    __syncthreads();
    for (int off = 1; off < NBLK; off <<= 1) {
        unsigned int t = (tid >= off) ? s[tid - off] : 0u;
        __syncthreads();
        s[tid] += t;
        __syncthreads();
    }
    g_bsum[tid] = s[tid] - v;
}

__global__ void scanC_kernel() {
    int i = blockIdx.x * blockDim.x + threadIdx.x;
    if (i < NB) g_hist[i] += g_bsum[i / SCAN_BLK];
}

__global__ void scatter_kernel(const float* __restrict__ positions, int B) {
    int i = blockIdx.x * blockDim.x + threadIdx.x;
    if (i >= B) return;
    float x = positions[3*i+0], y = positions[3*i+1], z = positions[3*i+2];
    unsigned int k = g_key[i];
    unsigned int dst = atomicAdd(&g_hist[k], 1u);
    g_spos[dst] = make_float4(x, y, z, __int_as_float(i));
}

// ---------------- main encoder: 4 lanes per point (corner-parallel) ----------
__global__ void __launch_bounds__(256) triplane_kernel(
    const float* __restrict__ table,
    float* __restrict__ out, int B, LP lp)
{
    __shared__ unsigned short s_lut[LUTCAP];
    int tid = threadIdx.x;
    for (int k = tid; k < LUTCAP; k += 256)
        s_lut[k] = g_lut[k];
    __syncthreads();

    // lane role: 4 consecutive lanes share one point; corner = lane & 3
    int gtid   = blockIdx.x * 256 + tid;
    int point  = gtid >> 2;
    int corner = tid & 3;
    int d0 = corner & 1;          // +offset on the plane's first axis
    int d1 = corner >> 1;         // +offset on the plane's second axis
    bool valid = (point < B);

    float4 p = g_spos[valid ? point : 0];
    float px = p.x, py = p.y, pz = p.z;
    int b = __float_as_int(p.w);

    const float2* t0 = (const float2*)table;
    const float2* t1 = t0 + MAXRES*MAXRES;
    const float2* t2 = t1 + MAXRES*MAXRES;

    float rx[4], ry[4];

#pragma unroll
    for (int l = 0; l < LEVELS; l++) {
        float resm1 = lp.resm1[l];
        int   off   = lp.off[l];

        float posx = __fadd_rn(__fmul_rn(px, resm1), 0.5f);
        float posy = __fadd_rn(__fmul_rn(py, resm1), 0.5f);
        float posz = __fadd_rn(__fmul_rn(pz, resm1), 0.5f);
        float gx = floorf(posx), gy = floorf(posy), gz = floorf(posz);
        float fx = posx - gx, fy = posy - gy, fz = posz - gz;
        int ix = (int)gx, iy = (int)gy, iz = (int)gz;

        // this lane's corner weights along each axis
        float wx0 = d0 ? fx : (1.0f - fx);   // axis as first dim
        float wy0 = d0 ? fy : (1.0f - fy);
        float wz0 = d0 ? fz : (1.0f - fz);
        float wx1 = d1 ? fx : (1.0f - fx);   // axis as second dim
        float wy1 = d1 ? fy : (1.0f - fy);
        float wz1 = d1 ? fz : (1.0f - fz);

        // master-grid coords via LUT (exact reference quantization)
        int cx0 = s_lut[off + ix + d0];
        int cy1 = s_lut[off + iy + d1];
        int cy0 = s_lut[off + iy + d0];
        int cz1 = s_lut[off + iz + d1];
        int cz0 = s_lut[off + iz + d0];
        int cx1 = s_lut[off + ix + d1];

        // one gather per plane (lanes = 8 points x 4 corners)
        float2 fa = __ldg(&t0[cx0 + cy1*MAXRES]);   // plane0 (x,y)
        float2 fb = __ldg(&t1[cy0 + cz1*MAXRES]);   // plane1 (y,z)
        float2 fc = __ldg(&t2[cz0 + cx1*MAXRES]);   // plane2 (z,x)

        float wa = wx0 * wy1;
        float wb = wy0 * wz1;
        float wc = wz0 * wx1;

        float pax = wa * fa.x, pay = wa * fa.y;
        float pbx = wb * fb.x, pby = wb * fb.y;
        float pcx = wc * fc.x, pcy = wc * fc.y;

        // sum the 4 corners within the lane group (xor 1, then 2 stays in-group)
        pax += __shfl_xor_sync(0xFFFFFFFFu, pax, 1);
        pay += __shfl_xor_sync(0xFFFFFFFFu, pay, 1);
        pbx += __shfl_xor_sync(0xFFFFFFFFu, pbx, 1);
        pby += __shfl_xor_sync(0xFFFFFFFFu, pby, 1);
        pcx += __shfl_xor_sync(0xFFFFFFFFu, pcx, 1);
        pcy += __shfl_xor_sync(0xFFFFFFFFu, pcy, 1);
        pax += __shfl_xor_sync(0xFFFFFFFFu, pax, 2);
        pay += __shfl_xor_sync(0xFFFFFFFFu, pay, 2);
        pbx += __shfl_xor_sync(0xFFFFFFFFu, pbx, 2);
        pby += __shfl_xor_sync(0xFFFFFFFFu, pby, 2);
        pcx += __shfl_xor_sync(0xFFFFFFFFu, pcx, 2);
        pcy += __shfl_xor_sync(0xFFFFFFFFu, pcy, 2);

        float vx = (pax * pbx) * pcx;
        float vy = (pay * pby) * pcy;

        // lane keeps levels [corner*4, corner*4+4)  (static indices, SEL)
        if ((l >> 2) == 0) { rx[l & 3] = (corner == 0) ? vx : ((l >> 2) == corner ? vx : rx[l & 3]); }
        // simpler: predicated keep
        rx[l & 3] = ((l >> 2) == corner) ? vx : rx[l & 3];
        ry[l & 3] = ((l >> 2) == corner) ? vy : ry[l & 3];
    }

    if (valid) {
        // out row = 128B; lanes 0-3 of the group each write 2 float4s
        float* row = out + (size_t)b * (2*LEVELS);
        float4* ox = (float4*)(row + corner*4);
        float4* oy = (float4*)(row + LEVELS + corner*4);
        *ox = make_float4(rx[0], rx[1], rx[2], rx[3]);
        *oy = make_float4(ry[0], ry[1], ry[2], ry[3]);
    }
}

// ---------------- launch -----------------------------------------------------
extern "C" void kernel_launch(void* const* d_in, const int* in_sizes, int n_in,
                              void* d_out, int out_size) {
    const float* positions = (const float*)d_in[0];
    const float* table     = (const float*)d_in[1];
    float* out             = (float*)d_out;
    int B = in_sizes[0] / 3;

    LP lp;
    double logb = log(2048.0 / 16.0) / 15.0;
    int acc = 0;
    for (int l = 0; l < LEVELS; l++) {
        double scale = 16.0 * exp((double)l * logb) - 1.0;
        int res = (int)ceil(scale) + 1;
        lp.resm1[l] = (float)(res - 1);
        lp.fres[l]  = (float)res;
        lp.off[l]   = acc;
        acc += res + 1;
    }
    lp.off[LEVELS] = acc;   // ~7400 < LUTCAP

    int threads = 256;
    int blocksP = (B + threads - 1) / threads;          // point-per-thread kernels
    int blocksM = (B * 4 + threads - 1) / threads;      // 4 lanes per point

    build_lut_kernel<<<(LUTCAP + 255) / 256, 256>>>(lp);
    zero_hist_kernel<<<NB / 256, 256>>>();
    hist_kernel<<<blocksP, threads>>>(positions, B);
    scanA_kernel<<<NBLK, SCAN_BLK>>>();
    scanB_kernel<<<1, NBLK>>>();
    scanC_kernel<<<NB / 256, 256>>>();
    scatter_kernel<<<blocksP, threads>>>(positions, B);
    triplane_kernel<<<blocksM, threads>>>(table, out, B, lp);
}

// round 6
// speedup vs baseline: 1.6680x; 1.4024x over previous
#include <cuda_runtime.h>
#include <math.h>

#define LEVELS 16
#define MAXRES 2048
#define BMAX   (1 << 20)
#define NB     (1 << 18)          // 18-bit Morton bins (6 bits/axis)
#define SCAN_BLK 1024
#define NBLK   (NB / SCAN_BLK)    // 256

struct LP { float resm1[LEVELS]; float fres[LEVELS]; };

// ---------------- scratch ----------------------------------------------------
__device__ unsigned int g_hist[NB];
__device__ unsigned int g_bsum[NBLK];
__device__ unsigned int g_key[BMAX];
__device__ float4       g_spos[BMAX];

// ---------------- helpers ----------------------------------------------------
__device__ __forceinline__ int quantize(float c, float fres) {
    return (int)__fmul_rn(__fdiv_rn(c, fres), 2047.0f);
}

__device__ __forceinline__ unsigned int expand3(unsigned int v) {
    v = (v | (v << 16)) & 0x030000FFu;
    v = (v | (v <<  8)) & 0x0300F00Fu;
    v = (v | (v <<  4)) & 0x030C30C3u;
    v = (v | (v <<  2)) & 0x09249249u;
    return v;
}

__device__ __forceinline__ unsigned int morton_key(float x, float y, float z) {
    int ix = (int)(x * 64.0f), iy = (int)(y * 64.0f), iz = (int)(z * 64.0f);
    unsigned int kx = (unsigned int)max(0, min(63, ix));
    unsigned int ky = (unsigned int)max(0, min(63, iy));
    unsigned int kz = (unsigned int)max(0, min(63, iz));
    return expand3(kx) | (expand3(ky) << 1) | (expand3(kz) << 2);
}

// ---------------- sort pipeline ----------------------------------------------
__global__ void zero_hist_kernel() {
    int i = blockIdx.x * blockDim.x + threadIdx.x;
    if (i < NB) g_hist[i] = 0u;
}

__global__ void hist_kernel(const float* __restrict__ positions, int B) {
    int i = blockIdx.x * blockDim.x + threadIdx.x;
    if (i >= B) return;
    float x = positions[3*i+0], y = positions[3*i+1], z = positions[3*i+2];
    unsigned int k = morton_key(x, y, z);
    g_key[i] = k;
    atomicAdd(&g_hist[k], 1u);
}

__global__ void scanA_kernel() {
    __shared__ unsigned int s[SCAN_BLK];
    int tid = threadIdx.x;
    int gid = blockIdx.x * SCAN_BLK + tid;
    unsigned int v = g_hist[gid];
    s[tid] = v;
    __syncthreads();
    for (int off = 1; off < SCAN_BLK; off <<= 1) {
        unsigned int t = (tid >= off) ? s[tid - off] : 0u;
        __syncthreads();
        s[tid] += t;
        __syncthreads();
    }
    g_hist[gid] = s[tid] - v;
    if (tid == SCAN_BLK - 1) g_bsum[blockIdx.x] = s[tid];
}

__global__ void scanB_kernel() {
    __shared__ unsigned int s[NBLK];
    int tid = threadIdx.x;
    unsigned int v = g_bsum[tid];
    s[tid] = v;
    __syncthreads();
    for (int off = 1; off < NBLK; off <<= 1) {
        unsigned int t = (tid >= off) ? s[tid - off] : 0u;
        __syncthreads();
        s[tid] += t;
        __syncthreads();
    }
    g_bsum[tid] = s[tid] - v;
}

__global__ void scanC_kernel() {
    int i = blockIdx.x * blockDim.x + threadIdx.x;
    if (i < NB) g_hist[i] += g_bsum[i / SCAN_BLK];
}

__global__ void scatter_kernel(const float* __restrict__ positions, int B) {
    int i = blockIdx.x * blockDim.x + threadIdx.x;
    if (i >= B) return;
    float x = positions[3*i+0], y = positions[3*i+1], z = positions[3*i+2];
    unsigned int k = g_key[i];
    unsigned int dst = atomicAdd(&g_hist[k], 1u);
    g_spos[dst] = make_float4(x, y, z, __int_as_float(i));
}

// ---------------- main encoder: 2 lanes per point (x-corner pair packed) -----
// lane parity d0 = first-axis corner. Thread loads the 2 second-axis corners
// for its first-axis corner on each plane (6 loads/level), sums the pair's
// partials via one shfl_xor(1) per plane per feature (6 shfl/level).
// Lane d0 keeps feature d0 only (16 result regs) and writes its 64B half-row.
__global__ void __launch_bounds__(256) triplane_kernel(
    const float* __restrict__ table,
    float* __restrict__ out, int B, LP lp)
{
    int gtid  = blockIdx.x * 256 + threadIdx.x;
    int point = gtid >> 1;
    int d0    = gtid & 1;
    bool valid = (point < B);

    float4 p = g_spos[valid ? point : 0];
    float px = p.x, py = p.y, pz = p.z;
    int b = __float_as_int(p.w);

    const float2* t0 = (const float2*)table;          // plane0 (x,y)
    const float2* t1 = t0 + MAXRES*MAXRES;            // plane1 (y,z)
    const float2* t2 = t1 + MAXRES*MAXRES;            // plane2 (z,x)

    float r[LEVELS];   // this lane's feature only

#pragma unroll
    for (int l = 0; l < LEVELS; l++) {
        float resm1 = lp.resm1[l];
        float fres  = lp.fres[l];

        // exact reference arithmetic (mul then add, no contraction)
        float posx = __fadd_rn(__fmul_rn(px, resm1), 0.5f);
        float posy = __fadd_rn(__fmul_rn(py, resm1), 0.5f);
        float posz = __fadd_rn(__fmul_rn(pz, resm1), 0.5f);
        float gx = floorf(posx), gy = floorf(posy), gz = floorf(posz);
        float fx = posx - gx, fy = posy - gy, fz = posz - gz;

        int cx0 = quantize(gx, fres), cx1 = quantize(gx + 1.0f, fres);
        int cy0 = quantize(gy, fres), cy1 = quantize(gy + 1.0f, fres);
        int cz0 = quantize(gz, fres), cz1 = quantize(gz + 1.0f, fres);

        int cxd = d0 ? cx1 : cx0;     // this lane's first-axis coords
        int cyd = d0 ? cy1 : cy0;
        int czd = d0 ? cz1 : cz0;

        // 6 gathers: for each plane, both second-axis corners at my first-axis corner
        float2 a0 = __ldg(&t0[cxd + cy0*MAXRES]);
        float2 a1 = __ldg(&t0[cxd + cy1*MAXRES]);
        float2 b0 = __ldg(&t1[cyd + cz0*MAXRES]);
        float2 b1 = __ldg(&t1[cyd + cz1*MAXRES]);
        float2 c0 = __ldg(&t2[czd + cx0*MAXRES]);
        float2 c1 = __ldg(&t2[czd + cx1*MAXRES]);

        float wxd = d0 ? fx : (1.0f - fx);
        float wyd = d0 ? fy : (1.0f - fy);
        float wzd = d0 ? fz : (1.0f - fz);
        float wy0 = 1.0f - fy, wy1 = fy;
        float wz0 = 1.0f - fz, wz1 = fz;
        float wx0 = 1.0f - fx, wx1 = fx;

        // in-thread second-axis sum, scaled by my first-axis weight
        float pax = wxd * (wy0*a0.x + wy1*a1.x);
        float pay = wxd * (wy0*a0.y + wy1*a1.y);
        float pbx = wyd * (wz0*b0.x + wz1*b1.x);
        float pby = wyd * (wz0*b0.y + wz1*b1.y);
        float pcx = wzd * (wx0*c0.x + wx1*c1.x);
        float pcy = wzd * (wx0*c0.y + wx1*c1.y);

        // cross-lane pair sum -> full bilinear value in both lanes
        pax += __shfl_xor_sync(0xFFFFFFFFu, pax, 1);
        pay += __shfl_xor_sync(0xFFFFFFFFu, pay, 1);
        pbx += __shfl_xor_sync(0xFFFFFFFFu, pbx, 1);
        pby += __shfl_xor_sync(0xFFFFFFFFu, pby, 1);
        pcx += __shfl_xor_sync(0xFFFFFFFFu, pcx, 1);
        pcy += __shfl_xor_sync(0xFFFFFFFFu, pcy, 1);

        float vx = (pax * pbx) * pcx;
        float vy = (pay * pby) * pcy;
        r[l] = d0 ? vy : vx;          // lane keeps its own feature
    }

    if (valid) {
        // out row: [x-feature 16 floats][y-feature 16 floats]; lane d0 writes its half
        float4* oh = (float4*)(out + (size_t)b * (2*LEVELS) + d0 * LEVELS);
#pragma unroll
        for (int k = 0; k < 4; k++)
            oh[k] = make_float4(r[4*k+0], r[4*k+1], r[4*k+2], r[4*k+3]);
    }
}

// ---------------- launch -----------------------------------------------------
extern "C" void kernel_launch(void* const* d_in, const int* in_sizes, int n_in,
                              void* d_out, int out_size) {
    const float* positions = (const float*)d_in[0];
    const float* table     = (const float*)d_in[1];
    float* out             = (float*)d_out;
    int B = in_sizes[0] / 3;

    LP lp;
    double logb = log(2048.0 / 16.0) / 15.0;
    for (int l = 0; l < LEVELS; l++) {
        double scale = 16.0 * exp((double)l * logb) - 1.0;
        int res = (int)ceil(scale) + 1;
        lp.resm1[l] = (float)(res - 1);
        lp.fres[l]  = (float)res;
    }

    int threads = 256;
    int blocksP = (B + threads - 1) / threads;       // 1 thread/point kernels
    int blocksM = (2*B + threads - 1) / threads;     // 2 lanes per point

    zero_hist_kernel<<<NB / 256, 256>>>();
    hist_kernel<<<blocksP, threads>>>(positions, B);
    scanA_kernel<<<NBLK, SCAN_BLK>>>();
    scanB_kernel<<<1, NBLK>>>();
    scanC_kernel<<<NB / 256, 256>>>();
    scatter_kernel<<<blocksP, threads>>>(positions, B);
    triplane_kernel<<<blocksM, threads>>>(table, out, B, lp);
}